// round 15
// baseline (speedup 1.0000x reference)
#include <cuda_runtime.h>
#include <math.h>
#include <stdint.h>

#define BB    128
#define TT    512
#define NNH   512
#define NCOLT 16
#define NGRP  8
#define NCTA  128
#define NJ    32     // columns per CTA
#define MB    16     // batches per CTA (= CTAs per group)
#define NTHR  512
#define WP    516
#define CP    516
#define RP17  17     // reduction pitch (coprime with 32)

// -------- persistent device state (b-major for h/c) --------
__device__ float g_h[2][BB * NNH];
__device__ float g_c[2][BB * NNH];
__device__ float g_fpart[NCOLT * BB];
__device__ unsigned int g_bars[NGRP * 32];

__global__ void hippo_init() {
    int idx = blockIdx.x * blockDim.x + threadIdx.x;
    if (idx < NGRP * 32) g_bars[idx] = 0u;
}

__device__ __forceinline__ void grp_arrive(unsigned int* barp) {
    __syncthreads();
    if (threadIdx.x == 0) {
        asm volatile("red.release.gpu.global.add.u32 [%0], 1;"
                     :: "l"(barp) : "memory");
    }
}
__device__ __forceinline__ void grp_wait(unsigned int* barp, unsigned int target) {
    if (threadIdx.x == 0) {
        unsigned int v;
        do {
            asm volatile("ld.acquire.gpu.global.u32 %0, [%1];"
                         : "=r"(v) : "l"(barp) : "memory");
        } while (v < target);
    }
    __syncthreads();
}

__device__ __forceinline__ void fma2(uint64_t& d, uint64_t a, uint64_t b) {
    asm("fma.rn.f32x2 %0, %1, %2, %0;" : "+l"(d) : "l"(a), "l"(b));
}
__device__ __forceinline__ float2 unpack2(uint64_t v) {
    float2 r;
    asm("mov.b64 {%0, %1}, %2;" : "=f"(r.x), "=f"(r.y) : "l"(v));
    return r;
}
__device__ __forceinline__ float tanh_fast(float v) {
    float r;
    asm("tanh.approx.f32 %0, %1;" : "=f"(r) : "f"(v));
    return r;
}
__device__ __forceinline__ void cpa16(float* dst, const float* src) {
    uint32_t d;
    asm("{ .reg .u64 t; cvta.to.shared.u64 t, %1; cvt.u32.u64 %0, t; }"
        : "=r"(d) : "l"(dst));
    asm volatile("cp.async.cg.shared.global [%0], [%1], 16;"
                 :: "r"(d), "l"(src) : "memory");
}
__device__ __forceinline__ void cpa_commit() {
    asm volatile("cp.async.commit_group;" ::: "memory");
}
__device__ __forceinline__ void cpa_wait_all() {
    asm volatile("cp.async.wait_group 0;" ::: "memory");
}
__device__ __forceinline__ float sum16(const float* rp) {
    float s0 = (rp[0] + rp[1]) + (rp[2] + rp[3]);
    float s1 = (rp[4] + rp[5]) + (rp[6] + rp[7]);
    float s2 = (rp[8] + rp[9]) + (rp[10] + rp[11]);
    float s3 = (rp[12] + rp[13]) + (rp[14] + rp[15]);
    return (s0 + s1) + (s2 + s3);
}

// smem floats: Wi[32*WP] Wh[32*WP] cS[16*CP] hS[16*CP] red[256*17] wf[512]
//              tile[32*17] fred[16*36] xs[16] f_s[16] wx[32] bb[32]
#define SM_FLOATS (2 * NJ * WP + 2 * MB * CP + 256 * RP17 + 512 + 32 * 17 + 16 * 36 + 16 + 16 + 32 + 32)
#define SM_BYTES  (SM_FLOATS * 4)

__global__ __launch_bounds__(NTHR, 1) void hippo_persistent(
    const float* __restrict__ x,
    const float* __restrict__ h0,
    const float* __restrict__ c0,
    const float* __restrict__ Wi,
    const float* __restrict__ bi,
    const float* __restrict__ Wh,
    const float* __restrict__ bh,
    const float* __restrict__ Wf,
    const float* __restrict__ bfv,
    const float* __restrict__ A_stack,
    const float* __restrict__ B_stack,
    float* __restrict__ out)
{
    extern __shared__ float sm[];
    float* Wi_s = sm;
    float* Wh_s = Wi_s + NJ * WP;
    float* cS   = Wh_s + NJ * WP;
    float* hS   = cS + MB * CP;
    float* red  = hS + MB * CP;             // 256*17
    float* wf_s = red + 256 * RP17;         // 512
    float* tile = wf_s + 512;               // 32*17
    float* fred = tile + 32 * 17;           // 16*36
    float* xs   = fred + 16 * 36;           // 16
    float* f_s  = xs + 16;                  // 16
    float* wx_s = f_s + 16;                 // 32
    float* bb_s = wx_s + 32;                // 32

    const int cta   = blockIdx.x;
    const int ct    = cta & (NCOLT - 1);
    const int grp   = cta >> 4;
    const int jbase = ct * NJ;
    const int bbase = grp * MB;
    const int tid   = threadIdx.x;

    // main-pass mapping: one k-chunk per warp (16 kc), 4j x 4b cells per thread
    const int kc   = tid >> 5;              // 0..15 (warp id)
    const int lane = tid & 31;
    const int jt   = lane & 7;              // j = jt + 8*jj
    const int bt   = lane >> 3;             // 0..3, b = bt + 4*bb
    const int kb   = kc * 32;

    // ownership bijection consistent with the 2-phase reduction
    const int j_own = (tid & 7) + 8 * (tid >> 7);
    const int b_own = ((tid >> 3) & 3) + 4 * ((tid >> 5) & 3);

    unsigned int* barp = &g_bars[grp * 32];

    // ---- one-time loads ----
    for (int i = tid; i < NJ * NNH; i += NTHR) {
        int r = i >> 9, k = i & 511;
        Wi_s[r * WP + k] = Wi[(jbase + r) * (NNH + 1) + 1 + k];
        Wh_s[r * WP + k] = Wh[(jbase + r) * (NNH + 1) + 1 + k];
    }
    for (int i = tid; i < NNH; i += NTHR) wf_s[i] = Wf[1 + i];
    if (tid < NJ) {
        wx_s[tid] = Wi[(jbase + tid) * (NNH + 1)] + Wh[(jbase + tid) * (NNH + 1)];
        bb_s[tid] = bi[jbase + tid] + bh[jbase + tid];
    }
    // ---- initial state staging (b-major, straight copy) ----
    #pragma unroll
    for (int it = 0; it < 4; ++it) {
        int idx = tid + 512 * it;
        int b = idx >> 7, kq = idx & 127;
        *(float4*)(cS + b * CP + 4 * kq) =
            *(const float4*)(c0 + (size_t)(bbase + b) * NNH + 4 * kq);
        *(float4*)(hS + b * CP + 4 * kq) =
            *(const float4*)(h0 + (size_t)(bbase + b) * NNH + 4 * kq);
    }
    __syncthreads();

    const float wf0 = Wf[0];
    const float bf0 = bfv[0];
    float* out_hs = out;
    float* out_cf = out + (size_t)BB * TT * NNH;

    const float* wiP = Wi_s + jt * WP + kb;   // + jj*8*WP
    const float* whP = Wh_s + jt * WP + kb;
    const float* cP  = cS + bt * CP + kb;     // + bb*4*CP
    const float* hP  = hS + bt * CP + kb;

    for (int t = 0; t < TT; ++t) {
        const int cur = t & 1;

        if (tid < MB) xs[tid] = __ldcg(&x[(size_t)(bbase + tid) * TT + t]);

        // L2 prefetch of this CTA's A tile (64KB, one 128B line per thread)
        {
            const float* ap = A_stack + ((size_t)t * NNH + jbase + (tid >> 4)) * NNH
                              + (tid & 15) * 32;
            asm volatile("prefetch.global.L2 [%0];" :: "l"(ap));
        }

        // ============ PASS 1: gates, 4j x 4b cells, k-range 32 ============
        uint64_t acc[4][4];
        #pragma unroll
        for (int jj = 0; jj < 4; ++jj)
            #pragma unroll
            for (int bb = 0; bb < 4; ++bb) acc[jj][bb] = 0;

        #pragma unroll
        for (int m = 0; m < 8; ++m) {
            const int ko = 4 * m;
            ulonglong2 wiv[4], whv[4], cv[4], hv[4];
            #pragma unroll
            for (int jj = 0; jj < 4; ++jj) {
                wiv[jj] = *(const ulonglong2*)(wiP + jj * 8 * WP + ko);
                whv[jj] = *(const ulonglong2*)(whP + jj * 8 * WP + ko);
            }
            #pragma unroll
            for (int bb = 0; bb < 4; ++bb) {
                cv[bb] = *(const ulonglong2*)(cP + bb * 4 * CP + ko);
                hv[bb] = *(const ulonglong2*)(hP + bb * 4 * CP + ko);
            }
            #pragma unroll
            for (int jj = 0; jj < 4; ++jj)
                #pragma unroll
                for (int bb = 0; bb < 4; ++bb) {
                    fma2(acc[jj][bb], wiv[jj].x, cv[bb].x);
                    fma2(acc[jj][bb], wiv[jj].y, cv[bb].y);
                    fma2(acc[jj][bb], whv[jj].x, hv[bb].x);
                    fma2(acc[jj][bb], whv[jj].y, hv[bb].y);
                }
        }

        // ====== gate reduction: 2 phases of 256 cells, conflict-free ======
        float gsum = 0.f;
        #pragma unroll
        for (int jj = 0; jj < 2; ++jj)
            #pragma unroll
            for (int bb = 0; bb < 4; ++bb) {
                float2 v = unpack2(acc[jj][bb]);
                red[(lane + 32 * (jj * 4 + bb)) * RP17 + kc] = v.x + v.y;
            }
        __syncthreads();
        if (tid < 256) gsum = sum16(red + tid * RP17);
        __syncthreads();
        #pragma unroll
        for (int jj = 2; jj < 4; ++jj)
            #pragma unroll
            for (int bb = 0; bb < 4; ++bb) {
                float2 v = unpack2(acc[jj][bb]);
                red[(lane + 32 * ((jj - 2) * 4 + bb)) * RP17 + kc] = v.x + v.y;
            }
        __syncthreads();
        if (tid >= 256) gsum = sum16(red + (tid - 256) * RP17);

        // ====== h_new ======
        {
            float gate = gsum + bb_s[j_own] + wx_s[j_own] * xs[b_own];
            float o  = 1.f / (1.f + __expf(-gate));
            float hn = o * tanh_fast(cS[b_own * CP + jbase + j_own]);
            tile[j_own * 17 + b_own] = hn;
            fred[b_own * 36 + j_own] = wf_s[jbase + j_own] * hn;
        }
        __syncthreads();
        {
            int bo = tid >> 5, jq = tid & 31;
            float v = tile[jq * 17 + bo];
            g_h[cur][(size_t)(bbase + bo) * NNH + jbase + jq] = v;
            out_hs[(size_t)(bbase + bo) * TT * NNH + (size_t)t * NNH + jbase + jq] = v;
        }
        if (tid < MB) {
            float s = 0.f;
            #pragma unroll
            for (int g4 = 0; g4 < 8; ++g4) {
                float4 v = *(const float4*)(fred + tid * 36 + 4 * g4);
                s += v.x + v.y + v.z + v.w;
            }
            g_fpart[ct * BB + bbase + tid] = s;
        }
        grp_arrive(barp);                         // #1: h_new + f partials visible

        // ============ PASS 2: P = A_t·c, depth-4 A ring (in #1's shadow) ======
        uint64_t pacc[4][4];
        #pragma unroll
        for (int jj = 0; jj < 4; ++jj)
            #pragma unroll
            for (int bb = 0; bb < 4; ++bb) pacc[jj][bb] = 0;

        const float* ArB = A_stack + ((size_t)t * NNH + jbase + jt) * NNH + kb;
        ulonglong2 ring[4][4];                    // [depth][jj]
        #pragma unroll
        for (int d = 0; d < 4; ++d)
            #pragma unroll
            for (int jj = 0; jj < 4; ++jj)
                ring[d][jj] = *(const ulonglong2*)(ArB + jj * 8 * NNH + 4 * d);

        #pragma unroll
        for (int m = 0; m < 8; ++m) {
            ulonglong2 cv[4];
            #pragma unroll
            for (int bb = 0; bb < 4; ++bb)
                cv[bb] = *(const ulonglong2*)(cP + bb * 4 * CP + 4 * m);
            #pragma unroll
            for (int jj = 0; jj < 4; ++jj) {
                ulonglong2 av = ring[m & 3][jj];
                #pragma unroll
                for (int bb = 0; bb < 4; ++bb) {
                    fma2(pacc[jj][bb], av.x, cv[bb].x);
                    fma2(pacc[jj][bb], av.y, cv[bb].y);
                }
            }
            if (m < 4) {
                #pragma unroll
                for (int jj = 0; jj < 4; ++jj)
                    ring[m & 3][jj] =
                        *(const ulonglong2*)(ArB + jj * 8 * NNH + 4 * (m + 4));
            }
        }

        // ====== P reduction: same 2-phase scheme ======
        float psum = 0.f;
        #pragma unroll
        for (int jj = 0; jj < 2; ++jj)
            #pragma unroll
            for (int bb = 0; bb < 4; ++bb) {
                float2 v = unpack2(pacc[jj][bb]);
                red[(lane + 32 * (jj * 4 + bb)) * RP17 + kc] = v.x + v.y;
            }
        __syncthreads();
        if (tid < 256) psum = sum16(red + tid * RP17);
        __syncthreads();
        #pragma unroll
        for (int jj = 2; jj < 4; ++jj)
            #pragma unroll
            for (int bb = 0; bb < 4; ++bb) {
                float2 v = unpack2(pacc[jj][bb]);
                red[(lane + 32 * ((jj - 2) * 4 + bb)) * RP17 + kc] = v.x + v.y;
            }
        __syncthreads();
        if (tid >= 256) psum = sum16(red + (tid - 256) * RP17);

        grp_wait(barp, (unsigned)(2 * t + 1) * MB);

        // ---- stage h for next step (cp.async) ----
        #pragma unroll
        for (int it = 0; it < 4; ++it) {
            int idx = tid + 512 * it;
            int b = idx >> 7, kq = idx & 127;
            cpa16(hS + b * CP + 4 * kq,
                  g_h[cur] + (size_t)(bbase + b) * NNH + 4 * kq);
        }
        cpa_commit();

        if (tid < MB) {
            float s = 0.f;
            #pragma unroll
            for (int q = 0; q < NCOLT; ++q)
                s += __ldcg(&g_fpart[q * BB + bbase + tid]);
            f_s[tid] = bf0 + wf0 * xs[tid] + s;
        }
        __syncthreads();

        // ====== c_new ======
        {
            float Bt = __ldg(&B_stack[t * NNH + jbase + j_own]);
            tile[j_own * 17 + b_own] = psum + f_s[b_own] * Bt;
        }
        __syncthreads();
        {
            int bo = tid >> 5, jq = tid & 31;
            float v = tile[jq * 17 + bo];
            g_c[cur][(size_t)(bbase + bo) * NNH + jbase + jq] = v;
            if (t == TT - 1)
                out_cf[(size_t)(bbase + bo) * NNH + jbase + jq] = v;
        }
        grp_arrive(barp);                             // #2
        grp_wait(barp, (unsigned)(2 * t + 2) * MB);

        // ---- stage c for next step (cp.async) ----
        #pragma unroll
        for (int it = 0; it < 4; ++it) {
            int idx = tid + 512 * it;
            int b = idx >> 7, kq = idx & 127;
            cpa16(cS + b * CP + 4 * kq,
                  g_c[cur] + (size_t)(bbase + b) * NNH + 4 * kq);
        }
        cpa_commit();
        cpa_wait_all();
        __syncthreads();
    }
}

extern "C" void kernel_launch(void* const* d_in, const int* in_sizes, int n_in,
                              void* d_out, int out_size) {
    const float* x   = (const float*)d_in[0];
    const float* h0  = (const float*)d_in[1];
    const float* c0  = (const float*)d_in[2];
    const float* Wi  = (const float*)d_in[3];
    const float* bi  = (const float*)d_in[4];
    const float* Wh  = (const float*)d_in[5];
    const float* bh  = (const float*)d_in[6];
    const float* Wf  = (const float*)d_in[7];
    const float* bf  = (const float*)d_in[8];
    const float* A_s = (const float*)d_in[9];
    const float* B_s = (const float*)d_in[10];
    float* out = (float*)d_out;

    cudaFuncSetAttribute(hippo_persistent,
                         cudaFuncAttributeMaxDynamicSharedMemorySize, SM_BYTES);
    hippo_init<<<1, 256>>>();
    hippo_persistent<<<NCTA, NTHR, SM_BYTES>>>(x, h0, c0, Wi, bi, Wh, bh, Wf, bf,
                                               A_s, B_s, out);
}

// round 16
// speedup vs baseline: 1.4301x; 1.4301x over previous
#include <cuda_runtime.h>
#include <math.h>
#include <stdint.h>

#define BB    128
#define TT    512
#define NNH   512
#define NCOLT 16
#define NGRP  8
#define NCTA  128
#define NJ    32     // columns per CTA
#define MB    16     // batches per CTA (= CTAs per group)
#define NTHR  512
#define WP    516
#define CP    516
#define RP9   9      // reduction pitch (coprime with 32)

// -------- persistent device state (b-major for h/c) --------
__device__ float g_h[2][BB * NNH];
__device__ float g_c[2][BB * NNH];
__device__ float g_fpart[NCOLT * BB];
__device__ unsigned int g_bars[NGRP * 32];

__global__ void hippo_init() {
    int idx = blockIdx.x * blockDim.x + threadIdx.x;
    if (idx < NGRP * 32) g_bars[idx] = 0u;
}

__device__ __forceinline__ void grp_arrive(unsigned int* barp) {
    __syncthreads();
    if (threadIdx.x == 0) {
        asm volatile("red.release.gpu.global.add.u32 [%0], 1;"
                     :: "l"(barp) : "memory");
    }
}
__device__ __forceinline__ void grp_wait(unsigned int* barp, unsigned int target) {
    if (threadIdx.x == 0) {
        unsigned int v;
        do {
            asm volatile("ld.acquire.gpu.global.u32 %0, [%1];"
                         : "=r"(v) : "l"(barp) : "memory");
        } while (v < target);
    }
    __syncthreads();
}

__device__ __forceinline__ void fma2(uint64_t& d, uint64_t a, uint64_t b) {
    asm("fma.rn.f32x2 %0, %1, %2, %0;" : "+l"(d) : "l"(a), "l"(b));
}
__device__ __forceinline__ float2 unpack2(uint64_t v) {
    float2 r;
    asm("mov.b64 {%0, %1}, %2;" : "=f"(r.x), "=f"(r.y) : "l"(v));
    return r;
}
__device__ __forceinline__ float tanh_fast(float v) {
    float r;
    asm("tanh.approx.f32 %0, %1;" : "=f"(r) : "f"(v));
    return r;
}
__device__ __forceinline__ void cpa16(float* dst, const float* src) {
    uint32_t d;
    asm("{ .reg .u64 t; cvta.to.shared.u64 t, %1; cvt.u32.u64 %0, t; }"
        : "=r"(d) : "l"(dst));
    asm volatile("cp.async.cg.shared.global [%0], [%1], 16;"
                 :: "r"(d), "l"(src) : "memory");
}
__device__ __forceinline__ void cpa_commit() {
    asm volatile("cp.async.commit_group;" ::: "memory");
}
__device__ __forceinline__ void cpa_wait_all() {
    asm volatile("cp.async.wait_group 0;" ::: "memory");
}

// smem floats: Wi[32*WP] Wh[32*WP] cS[16*CP] hS[16*CP] red[512*9] wf[512]
//              tile[32*17] fred[16*36] xs[16] f_s[16] wx[32] bb[32]
#define SM_FLOATS (2 * NJ * WP + 2 * MB * CP + 512 * RP9 + 512 + 32 * 17 + 16 * 36 + 16 + 16 + 32 + 32)
#define SM_BYTES  (SM_FLOATS * 4)

__global__ __launch_bounds__(NTHR, 1) void hippo_persistent(
    const float* __restrict__ x,
    const float* __restrict__ h0,
    const float* __restrict__ c0,
    const float* __restrict__ Wi,
    const float* __restrict__ bi,
    const float* __restrict__ Wh,
    const float* __restrict__ bh,
    const float* __restrict__ Wf,
    const float* __restrict__ bfv,
    const float* __restrict__ A_stack,
    const float* __restrict__ B_stack,
    float* __restrict__ out)
{
    extern __shared__ float sm[];
    float* Wi_s = sm;
    float* Wh_s = Wi_s + NJ * WP;
    float* cS   = Wh_s + NJ * WP;
    float* hS   = cS + MB * CP;
    float* red  = hS + MB * CP;             // 512*9
    float* wf_s = red + 512 * RP9;          // 512
    float* tile = wf_s + 512;               // 32*17
    float* fred = tile + 32 * 17;           // 16*36
    float* xs   = fred + 16 * 36;           // 16
    float* f_s  = xs + 16;                  // 16
    float* wx_s = f_s + 16;                 // 32
    float* bb_s = wx_s + 32;                // 32

    const int cta   = blockIdx.x;
    const int ct    = cta & (NCOLT - 1);
    const int grp   = cta >> 4;
    const int jbase = ct * NJ;
    const int bbase = grp * MB;
    const int tid   = threadIdx.x;

    // main-pass mapping: 8 k-chunks x (8 jt x 8 bt), k-range 64
    const int kc = tid >> 6;                // 0..7
    const int l6 = tid & 63;
    const int jt = l6 >> 3;                 // 0..7, j = jt + 8*jj
    const int bt = l6 & 7;                  // 0..7, b = bt + 8*bb
    const int kb = kc * 64;

    const int j_own = tid >> 4;             // 0..31
    const int b_own = tid & 15;             // 0..15

    unsigned int* barp = &g_bars[grp * 32];

    // ---- one-time loads ----
    for (int i = tid; i < NJ * NNH; i += NTHR) {
        int r = i >> 9, k = i & 511;
        Wi_s[r * WP + k] = Wi[(jbase + r) * (NNH + 1) + 1 + k];
        Wh_s[r * WP + k] = Wh[(jbase + r) * (NNH + 1) + 1 + k];
    }
    for (int i = tid; i < NNH; i += NTHR) wf_s[i] = Wf[1 + i];
    if (tid < NJ) {
        wx_s[tid] = Wi[(jbase + tid) * (NNH + 1)] + Wh[(jbase + tid) * (NNH + 1)];
        bb_s[tid] = bi[jbase + tid] + bh[jbase + tid];
    }
    // ---- initial state staging (b-major, straight copy) ----
    #pragma unroll
    for (int it = 0; it < 4; ++it) {
        int idx = tid + 512 * it;
        int b = idx >> 7, kq = idx & 127;
        *(float4*)(cS + b * CP + 4 * kq) =
            *(const float4*)(c0 + (size_t)(bbase + b) * NNH + 4 * kq);
        *(float4*)(hS + b * CP + 4 * kq) =
            *(const float4*)(h0 + (size_t)(bbase + b) * NNH + 4 * kq);
    }
    __syncthreads();

    const float wf0 = Wf[0];
    const float bf0 = bfv[0];
    float* out_hs = out;
    float* out_cf = out + (size_t)BB * TT * NNH;

    const float* wiP = Wi_s + jt * WP + kb;
    const float* whP = Wh_s + jt * WP + kb;
    const float* cP  = cS + bt * CP + kb;
    const float* hP  = hS + bt * CP + kb;

    for (int t = 0; t < TT; ++t) {
        const int cur = t & 1;

        if (tid < MB) xs[tid] = __ldcg(&x[(size_t)(bbase + tid) * TT + t]);

        // L2 prefetch of this CTA's A tile (64KB, one 128B line per thread)
        {
            const float* ap = A_stack + ((size_t)t * NNH + jbase + (tid >> 4)) * NNH
                              + (tid & 15) * 32;
            asm volatile("prefetch.global.L2 [%0];" :: "l"(ap));
        }

        // ========== FUSED PASS: gates (Wi·c + Wh·h) AND P = A_t·c ==========
        uint64_t acc[4][2], pacc[4][2];
        #pragma unroll
        for (int jj = 0; jj < 4; ++jj) {
            acc[jj][0] = 0;  acc[jj][1] = 0;
            pacc[jj][0] = 0; pacc[jj][1] = 0;
        }

        const float* ArB = A_stack + ((size_t)t * NNH + jbase + jt) * NNH + kb;
        ulonglong2 ring[2][4];                  // depth-2 A ring
        #pragma unroll
        for (int d = 0; d < 2; ++d)
            #pragma unroll
            for (int jj = 0; jj < 4; ++jj)
                ring[d][jj] = *(const ulonglong2*)(ArB + jj * 8 * NNH + 4 * d);

        #pragma unroll 4
        for (int m = 0; m < 16; ++m) {
            const int ko = 4 * m;
            ulonglong2 cv0 = *(const ulonglong2*)(cP + ko);
            ulonglong2 cv1 = *(const ulonglong2*)(cP + 8 * CP + ko);
            ulonglong2 hv0 = *(const ulonglong2*)(hP + ko);
            ulonglong2 hv1 = *(const ulonglong2*)(hP + 8 * CP + ko);
            #pragma unroll
            for (int jj = 0; jj < 4; ++jj) {
                ulonglong2 wiv = *(const ulonglong2*)(wiP + jj * 8 * WP + ko);
                ulonglong2 whv = *(const ulonglong2*)(whP + jj * 8 * WP + ko);
                ulonglong2 av  = ring[m & 1][jj];
                fma2(acc[jj][0], wiv.x, cv0.x);  fma2(acc[jj][0], wiv.y, cv0.y);
                fma2(acc[jj][0], whv.x, hv0.x);  fma2(acc[jj][0], whv.y, hv0.y);
                fma2(acc[jj][1], wiv.x, cv1.x);  fma2(acc[jj][1], wiv.y, cv1.y);
                fma2(acc[jj][1], whv.x, hv1.x);  fma2(acc[jj][1], whv.y, hv1.y);
                fma2(pacc[jj][0], av.x, cv0.x);  fma2(pacc[jj][0], av.y, cv0.y);
                fma2(pacc[jj][1], av.x, cv1.x);  fma2(pacc[jj][1], av.y, cv1.y);
            }
            if (m < 14) {
                #pragma unroll
                for (int jj = 0; jj < 4; ++jj)
                    ring[m & 1][jj] =
                        *(const ulonglong2*)(ArB + jj * 8 * NNH + 4 * (m + 2));
            }
        }

        // ====== single-phase gate reduction over 8 k-chunks ======
        #pragma unroll
        for (int jj = 0; jj < 4; ++jj)
            #pragma unroll
            for (int bb = 0; bb < 2; ++bb) {
                float2 v = unpack2(acc[jj][bb]);
                int cell = (jt + 8 * jj) * 16 + bt + 8 * bb;
                red[cell * RP9 + kc] = v.x + v.y;
            }
        __syncthreads();
        float gsum;
        {
            const float* rp = red + tid * RP9;
            gsum = ((rp[0] + rp[1]) + (rp[2] + rp[3]))
                 + ((rp[4] + rp[5]) + (rp[6] + rp[7]));
        }

        // ====== h_new ======
        {
            float gate = gsum + bb_s[j_own] + wx_s[j_own] * xs[b_own];
            float o  = 1.f / (1.f + __expf(-gate));
            float hn = o * tanh_fast(cS[b_own * CP + jbase + j_own]);
            tile[j_own * 17 + b_own] = hn;
            fred[b_own * 36 + j_own] = wf_s[jbase + j_own] * hn;
        }
        __syncthreads();
        {
            int bo = tid >> 5, jq = tid & 31;
            float v = tile[jq * 17 + bo];
            g_h[cur][(size_t)(bbase + bo) * NNH + jbase + jq] = v;
            out_hs[(size_t)(bbase + bo) * TT * NNH + (size_t)t * NNH + jbase + jq] = v;
        }
        if (tid < MB) {
            float s = 0.f;
            #pragma unroll
            for (int g4 = 0; g4 < 8; ++g4) {
                float4 v = *(const float4*)(fred + tid * 36 + 4 * g4);
                s += v.x + v.y + v.z + v.w;
            }
            g_fpart[ct * BB + bbase + tid] = s;
        }
        grp_arrive(barp);                         // #1: h_new + f partials visible

        // ====== single-phase P reduction (in barrier #1's shadow) ======
        #pragma unroll
        for (int jj = 0; jj < 4; ++jj)
            #pragma unroll
            for (int bb = 0; bb < 2; ++bb) {
                float2 v = unpack2(pacc[jj][bb]);
                int cell = (jt + 8 * jj) * 16 + bt + 8 * bb;
                red[cell * RP9 + kc] = v.x + v.y;
            }
        __syncthreads();
        float psum;
        {
            const float* rp = red + tid * RP9;
            psum = ((rp[0] + rp[1]) + (rp[2] + rp[3]))
                 + ((rp[4] + rp[5]) + (rp[6] + rp[7]));
        }

        grp_wait(barp, (unsigned)(2 * t + 1) * MB);

        // ---- stage h for next step (cp.async) ----
        #pragma unroll
        for (int it = 0; it < 4; ++it) {
            int idx = tid + 512 * it;
            int b = idx >> 7, kq = idx & 127;
            cpa16(hS + b * CP + 4 * kq,
                  g_h[cur] + (size_t)(bbase + b) * NNH + 4 * kq);
        }
        cpa_commit();

        if (tid < MB) {
            float s = 0.f;
            #pragma unroll
            for (int q = 0; q < NCOLT; ++q)
                s += __ldcg(&g_fpart[q * BB + bbase + tid]);
            f_s[tid] = bf0 + wf0 * xs[tid] + s;
        }
        __syncthreads();

        // ====== c_new ======
        {
            float Bt = __ldg(&B_stack[t * NNH + jbase + j_own]);
            tile[j_own * 17 + b_own] = psum + f_s[b_own] * Bt;
        }
        __syncthreads();
        {
            int bo = tid >> 5, jq = tid & 31;
            float v = tile[jq * 17 + bo];
            g_c[cur][(size_t)(bbase + bo) * NNH + jbase + jq] = v;
            if (t == TT - 1)
                out_cf[(size_t)(bbase + bo) * NNH + jbase + jq] = v;
        }
        grp_arrive(barp);                             // #2
        grp_wait(barp, (unsigned)(2 * t + 2) * MB);

        // ---- stage c for next step (cp.async) ----
        #pragma unroll
        for (int it = 0; it < 4; ++it) {
            int idx = tid + 512 * it;
            int b = idx >> 7, kq = idx & 127;
            cpa16(cS + b * CP + 4 * kq,
                  g_c[cur] + (size_t)(bbase + b) * NNH + 4 * kq);
        }
        cpa_commit();
        cpa_wait_all();
        __syncthreads();
    }
}

extern "C" void kernel_launch(void* const* d_in, const int* in_sizes, int n_in,
                              void* d_out, int out_size) {
    const float* x   = (const float*)d_in[0];
    const float* h0  = (const float*)d_in[1];
    const float* c0  = (const float*)d_in[2];
    const float* Wi  = (const float*)d_in[3];
    const float* bi  = (const float*)d_in[4];
    const float* Wh  = (const float*)d_in[5];
    const float* bh  = (const float*)d_in[6];
    const float* Wf  = (const float*)d_in[7];
    const float* bf  = (const float*)d_in[8];
    const float* A_s = (const float*)d_in[9];
    const float* B_s = (const float*)d_in[10];
    float* out = (float*)d_out;

    cudaFuncSetAttribute(hippo_persistent,
                         cudaFuncAttributeMaxDynamicSharedMemorySize, SM_BYTES);
    hippo_init<<<1, 256>>>();
    hippo_persistent<<<NCTA, NTHR, SM_BYTES>>>(x, h0, c0, Wi, bi, Wh, bh, Wf, bf,
                                               A_s, B_s, out);
}